// round 5
// baseline (speedup 1.0000x reference)
#include <cuda_runtime.h>
#include <cuda_bf16.h>

#define N_NODES   200000
#define N_EDGES   6400000
#define N_GRAPHS  512
#define DIM_IN    128
#define HID       32
#define BN_EPS    1e-5f

#define ENC_OFF   0
#define DEC_OFF   (N_NODES * HID)                     // 6,400,000
#define GLOB_OFF  (N_NODES * HID + N_NODES * DIM_IN)  // 32,000,000

#define FULLMASK  0xffffffffu

// ---------------- scratch (device globals; no cudaMalloc allowed) ----------
__device__ int   g_cnt[N_NODES];
__device__ int   g_rowptr[N_NODES + 1];
__device__ int   g_cursor[N_NODES];
__device__ int   g_col[N_EDGES];
__device__ int   g_goff[N_GRAPHS + 1];
__device__ float g_stats[10 * 64];                    // per layer: sum[32], sumsq[32]
__device__ __align__(16) float g_xp[N_NODES * HID];
__device__ __align__(16) float g_bufA[N_NODES * HID];
__device__ __align__(16) float g_bufB[N_NODES * HID];

// ---------------- setup kernels --------------------------------------------
__global__ void zero_kernel() {
    int i = blockIdx.x * 256 + threadIdx.x;
    if (i < N_NODES) g_cnt[i] = 0;
    if (i < 10 * 64) g_stats[i] = 0.f;
}

__global__ void hist_kernel(const int* __restrict__ dst) {
    int e = blockIdx.x * 256 + threadIdx.x;   // exact: 25000*256 == N_EDGES
    atomicAdd(&g_cnt[dst[e]], 1);
}

// single-block exclusive scan of g_cnt -> g_rowptr / g_cursor
__global__ void scan_kernel() {
    __shared__ int wtot[32];
    __shared__ int carry;
    int tid = threadIdx.x, lane = tid & 31, wid = tid >> 5;
    if (tid == 0) carry = 0;
    __syncthreads();
    for (int base = 0; base < N_NODES; base += 1024) {
        int i = base + tid;
        int v = (i < N_NODES) ? g_cnt[i] : 0;
        int incl = v;
        #pragma unroll
        for (int off = 1; off < 32; off <<= 1) {
            int t = __shfl_up_sync(FULLMASK, incl, off);
            if (lane >= off) incl += t;
        }
        if (lane == 31) wtot[wid] = incl;
        __syncthreads();
        if (wid == 0) {
            int wv = wtot[lane];
            #pragma unroll
            for (int off = 1; off < 32; off <<= 1) {
                int t = __shfl_up_sync(FULLMASK, wv, off);
                if (lane >= off) wv += t;
            }
            wtot[lane] = wv;
        }
        __syncthreads();
        int wex = wid ? wtot[wid - 1] : 0;
        int excl = carry + wex + incl - v;
        if (i < N_NODES) { g_rowptr[i] = excl; g_cursor[i] = excl; }
        int tile_total = wtot[31];
        __syncthreads();
        if (tid == 0) carry += tile_total;
        __syncthreads();
    }
    if (threadIdx.x == 0) g_rowptr[N_NODES] = carry;
}

__global__ void offsets_kernel(const int* __restrict__ batch) {
    int g = threadIdx.x;
    if (g > N_GRAPHS) return;
    if (g == N_GRAPHS) { g_goff[g] = N_NODES; return; }
    int lo = 0, hi = N_NODES;
    while (lo < hi) {
        int mid = (lo + hi) >> 1;
        if (batch[mid] < g) lo = mid + 1; else hi = mid;
    }
    g_goff[g] = lo;
}

__global__ void permute_kernel(const int* __restrict__ src, const int* __restrict__ dst) {
    int e = blockIdx.x * 256 + threadIdx.x;
    int d = dst[e];
    int p = atomicAdd(&g_cursor[d], 1);
    g_col[p] = src[e];
}

// ---------------- projection: xp = x @ e0_w1 (128 -> 32) -------------------
__global__ void __launch_bounds__(256) proj_kernel(const float* __restrict__ x,
                                                   const float* __restrict__ w1) {
    __shared__ float ws[DIM_IN * HID];
    for (int i = threadIdx.x; i < DIM_IN * HID; i += 256) ws[i] = w1[i];
    __syncthreads();
    int lane = threadIdx.x & 31, wid = threadIdx.x >> 5;
    int n = blockIdx.x * 8 + wid;
    const float* xr = x + (long long)n * DIM_IN;
    float x0 = xr[lane], x1 = xr[32 + lane], x2 = xr[64 + lane], x3 = xr[96 + lane];
    float acc0 = 0.f, acc1 = 0.f;
    #pragma unroll
    for (int k = 0; k < 32; k++) {
        acc0 += __shfl_sync(FULLMASK, x0, k) * ws[k * 32 + lane];
        acc1 += __shfl_sync(FULLMASK, x1, k) * ws[(32 + k) * 32 + lane];
    }
    #pragma unroll
    for (int k = 0; k < 32; k++) {
        acc0 += __shfl_sync(FULLMASK, x2, k) * ws[(64 + k) * 32 + lane];
        acc1 += __shfl_sync(FULLMASK, x3, k) * ws[(96 + k) * 32 + lane];
    }
    g_xp[n * 32 + lane] = acc0 + acc1;
}

// ---------------- fused GIN layer: gather-sum + MLP + BN stats -------------
template <bool APPLY_W1>
__global__ void __launch_bounds__(256) gin_kernel(
    const float* __restrict__ xin, float* __restrict__ outp,
    const float* __restrict__ w1, const float* __restrict__ b1,
    const float* __restrict__ w2, const float* __restrict__ b2, int sl)
{
    int lane = threadIdx.x & 31, wid = threadIdx.x >> 5;
    int n = blockIdx.x * 8 + wid;

    float rw1[32], rw2[32];
    if (APPLY_W1) {
        #pragma unroll
        for (int k = 0; k < 32; k++) rw1[k] = w1[k * 32 + lane];
    }
    #pragma unroll
    for (int k = 0; k < 32; k++) rw2[k] = w2[k * 32 + lane];
    float rb1 = b1[lane], rb2 = b2[lane];

    __shared__ float ssum[32], ssq[32];
    if (threadIdx.x < 32) { ssum[threadIdx.x] = 0.f; ssq[threadIdx.x] = 0.f; }
    __syncthreads();

    int start = g_rowptr[n], end = g_rowptr[n + 1];
    float a0 = xin[n * 32 + lane], a1 = 0.f, a2 = 0.f, a3 = 0.f;

    int b0 = start;
    for (; b0 + 32 <= end; b0 += 32) {
        int idx = g_col[b0 + lane];
        #pragma unroll
        for (int k = 0; k < 32; k += 4) {
            int n0 = __shfl_sync(FULLMASK, idx, k);
            int n1 = __shfl_sync(FULLMASK, idx, k + 1);
            int n2 = __shfl_sync(FULLMASK, idx, k + 2);
            int n3 = __shfl_sync(FULLMASK, idx, k + 3);
            a0 += xin[n0 * 32 + lane];
            a1 += xin[n1 * 32 + lane];
            a2 += xin[n2 * 32 + lane];
            a3 += xin[n3 * 32 + lane];
        }
    }
    int rem = end - b0;
    if (rem > 0) {
        int idx = (lane < rem) ? g_col[b0 + lane] : 0;
        for (int k = 0; k < rem; k++) {
            int nb = __shfl_sync(FULLMASK, idx, k);
            a0 += xin[nb * 32 + lane];
        }
    }
    float t = (a0 + a1) + (a2 + a3);

    float h1;
    if (APPLY_W1) {
        h1 = rb1;
        #pragma unroll
        for (int k = 0; k < 32; k++) h1 += __shfl_sync(FULLMASK, t, k) * rw1[k];
    } else {
        h1 = t + rb1;
    }
    h1 = fmaxf(h1, 0.f);

    float h2 = rb2;
    #pragma unroll
    for (int k = 0; k < 32; k++) h2 += __shfl_sync(FULLMASK, h1, k) * rw2[k];
    h2 = fmaxf(h2, 0.f);

    outp[n * 32 + lane] = h2;
    atomicAdd(&ssum[lane], h2);
    atomicAdd(&ssq[lane], h2 * h2);
    __syncthreads();
    if (threadIdx.x < 32)
        atomicAdd(&g_stats[sl * 64 + threadIdx.x], ssum[threadIdx.x]);
    else if (threadIdx.x < 64)
        atomicAdd(&g_stats[sl * 64 + threadIdx.x], ssq[threadIdx.x - 32]);
}

// ---------------- last decoder layer: gather + MLP (32 -> 128), ReLU -------
__global__ void __launch_bounds__(256) gin_last_kernel(
    const float* __restrict__ xin, float* __restrict__ outp,
    const float* __restrict__ w1, const float* __restrict__ b1,
    const float* __restrict__ w2L, const float* __restrict__ b2L)
{
    __shared__ float wLs[HID * DIM_IN];
    for (int i = threadIdx.x; i < HID * DIM_IN; i += 256) wLs[i] = w2L[i];
    int lane = threadIdx.x & 31, wid = threadIdx.x >> 5;
    int n = blockIdx.x * 8 + wid;

    float rw1[32];
    #pragma unroll
    for (int k = 0; k < 32; k++) rw1[k] = w1[k * 32 + lane];
    float rb1 = b1[lane];
    __syncthreads();

    int start = g_rowptr[n], end = g_rowptr[n + 1];
    float a0 = xin[n * 32 + lane], a1 = 0.f, a2 = 0.f, a3 = 0.f;
    int b0 = start;
    for (; b0 + 32 <= end; b0 += 32) {
        int idx = g_col[b0 + lane];
        #pragma unroll
        for (int k = 0; k < 32; k += 4) {
            int n0 = __shfl_sync(FULLMASK, idx, k);
            int n1 = __shfl_sync(FULLMASK, idx, k + 1);
            int n2 = __shfl_sync(FULLMASK, idx, k + 2);
            int n3 = __shfl_sync(FULLMASK, idx, k + 3);
            a0 += xin[n0 * 32 + lane];
            a1 += xin[n1 * 32 + lane];
            a2 += xin[n2 * 32 + lane];
            a3 += xin[n3 * 32 + lane];
        }
    }
    int rem = end - b0;
    if (rem > 0) {
        int idx = (lane < rem) ? g_col[b0 + lane] : 0;
        for (int k = 0; k < rem; k++) {
            int nb = __shfl_sync(FULLMASK, idx, k);
            a0 += xin[nb * 32 + lane];
        }
    }
    float t = (a0 + a1) + (a2 + a3);

    float h1 = rb1;
    #pragma unroll
    for (int k = 0; k < 32; k++) h1 += __shfl_sync(FULLMASK, t, k) * rw1[k];
    h1 = fmaxf(h1, 0.f);

    float o0 = b2L[lane], o1 = b2L[32 + lane], o2 = b2L[64 + lane], o3 = b2L[96 + lane];
    #pragma unroll
    for (int k = 0; k < 32; k++) {
        float hk = __shfl_sync(FULLMASK, h1, k);
        const float* wr = &wLs[k * 128];
        o0 += hk * wr[lane];
        o1 += hk * wr[32 + lane];
        o2 += hk * wr[64 + lane];
        o3 += hk * wr[96 + lane];
    }
    float* orow = outp + (long long)n * 128;
    orow[lane]      = fmaxf(o0, 0.f);
    orow[32 + lane] = fmaxf(o1, 0.f);
    orow[64 + lane] = fmaxf(o2, 0.f);
    orow[96 + lane] = fmaxf(o3, 0.f);
}

// ---------------- BatchNorm apply (train-mode batch stats) -----------------
__global__ void __launch_bounds__(256) bn_kernel(
    const float* __restrict__ pre, float* __restrict__ outp, int sl,
    const float* __restrict__ gamma, const float* __restrict__ beta,
    float* __restrict__ encout)
{
    __shared__ float sa[32], sb[32];
    if (threadIdx.x < 32) {
        float s = g_stats[sl * 64 + threadIdx.x];
        float q = g_stats[sl * 64 + 32 + threadIdx.x];
        const float invn = 1.f / (float)N_NODES;
        float m = s * invn;
        float v = fmaxf(q * invn - m * m, 0.f);
        float a = gamma[threadIdx.x] * rsqrtf(v + BN_EPS);
        sa[threadIdx.x] = a;
        sb[threadIdx.x] = beta[threadIdx.x] - a * m;
    }
    __syncthreads();
    int i = blockIdx.x * 256 + threadIdx.x;         // float4 index; exact coverage
    int f0 = (i & 7) * 4;
    float4 v4 = ((const float4*)pre)[i];
    v4.x = sa[f0]     * v4.x + sb[f0];
    v4.y = sa[f0 + 1] * v4.y + sb[f0 + 1];
    v4.z = sa[f0 + 2] * v4.z + sb[f0 + 2];
    v4.w = sa[f0 + 3] * v4.w + sb[f0 + 3];
    ((float4*)outp)[i] = v4;
    if (encout) ((float4*)encout)[i] = v4;
}

// ---------------- global add pool over contiguous graph ranges -------------
__global__ void __launch_bounds__(256) pool_kernel(
    const float* __restrict__ src, float* __restrict__ dst, int layer)
{
    int g = blockIdx.x;
    int s = g_goff[g], e = g_goff[g + 1];
    int f = threadIdx.x & 31, sub = threadIdx.x >> 5;
    float p = 0.f;
    for (int r = s + sub; r < e; r += 8) p += src[r * 32 + f];
    __shared__ float sp[256];
    sp[threadIdx.x] = p;
    __syncthreads();
    if (threadIdx.x < 32) {
        float t = sp[f];
        #pragma unroll
        for (int j = 1; j < 8; j++) t += sp[j * 32 + f];
        dst[g * (5 * HID) + layer * HID + f] = t;
    }
}

// ---------------- launch ---------------------------------------------------
extern "C" void kernel_launch(void* const* d_in, const int* in_sizes, int n_in,
                              void* d_out, int out_size) {
    const float* x        = (const float*)d_in[0];
    const int*   ei       = (const int*)d_in[1];
    const int*   batch    = (const int*)d_in[2];
    const float* e0_w1    = (const float*)d_in[3];
    const float* e0_b1    = (const float*)d_in[4];
    const float* e0_w2    = (const float*)d_in[5];
    const float* e0_b2    = (const float*)d_in[6];
    const float* enc_w1   = (const float*)d_in[7];
    const float* enc_b1   = (const float*)d_in[8];
    const float* enc_w2   = (const float*)d_in[9];
    const float* enc_b2   = (const float*)d_in[10];
    const float* enc_gamma= (const float*)d_in[11];
    const float* enc_beta = (const float*)d_in[12];
    const float* dec_w1   = (const float*)d_in[13];
    const float* dec_b1   = (const float*)d_in[14];
    const float* dec_w2   = (const float*)d_in[15];
    const float* dec_b2   = (const float*)d_in[16];
    const float* dec_w2_last = (const float*)d_in[17];
    const float* dec_b2_last = (const float*)d_in[18];
    const float* dec_gamma= (const float*)d_in[19];
    const float* dec_beta = (const float*)d_in[20];
    float* out = (float*)d_out;

    const int* srcp = ei;
    const int* dstp = ei + N_EDGES;

    float *pA, *pB, *pXP;
    cudaGetSymbolAddress((void**)&pA,  g_bufA);
    cudaGetSymbolAddress((void**)&pB,  g_bufB);
    cudaGetSymbolAddress((void**)&pXP, g_xp);

    // CSR build + graph offsets (once per launch)
    zero_kernel<<<782, 256>>>();
    hist_kernel<<<25000, 256>>>(dstp);
    scan_kernel<<<1, 1024>>>();
    offsets_kernel<<<1, 1024>>>(batch);
    permute_kernel<<<25000, 256>>>(srcp, dstp);

    // layer-0 projection (linearity trick: 128-dim aggregation -> 32-dim)
    proj_kernel<<<25000, 256>>>(x, e0_w1);

    // ----- encoder -----
    gin_kernel<false><<<25000, 256>>>(pXP, pB, nullptr, e0_b1, e0_w2, e0_b2, 0);
    bn_kernel<<<6250, 256>>>(pB, pA, 0, enc_gamma, enc_beta, nullptr);
    pool_kernel<<<N_GRAPHS, 256>>>(pA, out + GLOB_OFF, 0);
    for (int L = 1; L < 5; L++) {
        gin_kernel<true><<<25000, 256>>>(pA, pB,
            enc_w1 + (L - 1) * 1024, enc_b1 + (L - 1) * 32,
            enc_w2 + (L - 1) * 1024, enc_b2 + (L - 1) * 32, L);
        bn_kernel<<<6250, 256>>>(pB, pA, L, enc_gamma + L * 32, enc_beta + L * 32,
                                 (L == 4) ? (out + ENC_OFF) : nullptr);
        pool_kernel<<<N_GRAPHS, 256>>>(pA, out + GLOB_OFF, L);
    }

    // ----- decoder -----
    for (int L = 0; L < 4; L++) {
        gin_kernel<true><<<25000, 256>>>(pA, pB,
            dec_w1 + L * 1024, dec_b1 + L * 32,
            dec_w2 + L * 1024, dec_b2 + L * 32, 5 + L);
        bn_kernel<<<6250, 256>>>(pB, pA, 5 + L, dec_gamma + L * 32, dec_beta + L * 32, nullptr);
    }
    gin_last_kernel<<<25000, 256>>>(pA, out + DEC_OFF,
        dec_w1 + 4 * 1024, dec_b1 + 4 * 32, dec_w2_last, dec_b2_last);
}

// round 6
// speedup vs baseline: 1.3253x; 1.3253x over previous
#include <cuda_runtime.h>
#include <cuda_bf16.h>

#define N_NODES   200000
#define N_EDGES   6400000
#define N_GRAPHS  512
#define DIM_IN    128
#define HID       32
#define BN_EPS    1e-5f

#define ENC_OFF   0
#define DEC_OFF   (N_NODES * HID)                     // 6,400,000
#define GLOB_OFF  (N_NODES * HID + N_NODES * DIM_IN)  // 32,000,000

#define FULLMASK  0xffffffffu
#define SCAN_BLOCKS 196

// ---------------- scratch (device globals; no cudaMalloc allowed) ----------
__device__ int   g_cnt[N_NODES];
__device__ int   g_rowptr[N_NODES + 1];
__device__ int   g_cursor[N_NODES];
__device__ int   g_col[N_EDGES];
__device__ int   g_bsum[SCAN_BLOCKS];
__device__ int   g_boff[SCAN_BLOCKS];
__device__ int   g_goff[N_GRAPHS + 1];
__device__ float g_stats[10 * 64];                    // per layer: sum[32], sumsq[32]
__device__ __align__(16) float g_xp[N_NODES * HID];
__device__ __align__(16) float g_bufA[N_NODES * HID];
__device__ __align__(16) float g_bufT[N_NODES * HID];

// ---------------- setup kernels --------------------------------------------
__global__ void init_kernel() {
    int i = blockIdx.x * 256 + threadIdx.x;
    if (i < N_NODES) g_cnt[i] = 0;
    if (i < 10 * 64) g_stats[i] = 0.f;
}

__global__ void offsets_kernel(const int* __restrict__ batch) {
    int g = blockIdx.x * 256 + threadIdx.x;
    if (g > N_GRAPHS) return;
    if (g == N_GRAPHS) { g_goff[g] = N_NODES; return; }
    int lo = 0, hi = N_NODES;
    while (lo < hi) {
        int mid = (lo + hi) >> 1;
        if (batch[mid] < g) lo = mid + 1; else hi = mid;
    }
    g_goff[g] = lo;
}

__global__ void hist_kernel(const int* __restrict__ dst) {
    int e = blockIdx.x * 256 + threadIdx.x;   // exact: 25000*256 == N_EDGES
    atomicAdd(&g_cnt[dst[e]], 1);
}

// --- 3-phase exclusive scan of g_cnt -> g_rowptr / g_cursor ----------------
__global__ void scan_block_kernel() {      // SCAN_BLOCKS x 1024
    __shared__ int wtot[32];
    int tid = threadIdx.x, lane = tid & 31, wid = tid >> 5;
    int i = blockIdx.x * 1024 + tid;
    int v = (i < N_NODES) ? g_cnt[i] : 0;
    int incl = v;
    #pragma unroll
    for (int off = 1; off < 32; off <<= 1) {
        int t = __shfl_up_sync(FULLMASK, incl, off);
        if (lane >= off) incl += t;
    }
    if (lane == 31) wtot[wid] = incl;
    __syncthreads();
    if (wid == 0) {
        int wv = wtot[lane];
        #pragma unroll
        for (int off = 1; off < 32; off <<= 1) {
            int t = __shfl_up_sync(FULLMASK, wv, off);
            if (lane >= off) wv += t;
        }
        wtot[lane] = wv;
    }
    __syncthreads();
    int excl = (wid ? wtot[wid - 1] : 0) + incl - v;
    if (i < N_NODES) g_rowptr[i] = excl;
    if (tid == 1023) g_bsum[blockIdx.x] = wtot[31];
}

__global__ void scan_tops_kernel() {       // 1 x 256
    __shared__ int wt[8];
    int tid = threadIdx.x, lane = tid & 31, wid = tid >> 5;
    int v = (tid < SCAN_BLOCKS) ? g_bsum[tid] : 0;
    int incl = v;
    #pragma unroll
    for (int off = 1; off < 32; off <<= 1) {
        int t = __shfl_up_sync(FULLMASK, incl, off);
        if (lane >= off) incl += t;
    }
    if (lane == 31) wt[wid] = incl;
    __syncthreads();
    if (wid == 0) {
        int wv = (lane < 8) ? wt[lane] : 0;
        #pragma unroll
        for (int off = 1; off < 32; off <<= 1) {
            int t = __shfl_up_sync(FULLMASK, wv, off);
            if (lane >= off) wv += t;
        }
        if (lane < 8) wt[lane] = wv;
    }
    __syncthreads();
    int excl = (wid ? wt[wid - 1] : 0) + incl - v;
    if (tid < SCAN_BLOCKS) g_boff[tid] = excl;
}

__global__ void scan_add_kernel() {        // SCAN_BLOCKS x 1024
    int i = blockIdx.x * 1024 + threadIdx.x;
    if (i < N_NODES) {
        int r = g_rowptr[i] + g_boff[blockIdx.x];
        g_rowptr[i] = r;
        g_cursor[i] = r;
    }
    if (i == 0) g_rowptr[N_NODES] = N_EDGES;
}

__global__ void permute_kernel(const int* __restrict__ src, const int* __restrict__ dst) {
    int e = blockIdx.x * 256 + threadIdx.x;
    int d = dst[e];
    int p = atomicAdd(&g_cursor[d], 1);
    g_col[p] = src[e];
}

// ---------------- projection: xp = x @ e0_w1 (128 -> 32) -------------------
__global__ void __launch_bounds__(256) proj_kernel(const float* __restrict__ x,
                                                   const float* __restrict__ w1) {
    __shared__ float ws[DIM_IN * HID];
    for (int i = threadIdx.x; i < DIM_IN * HID; i += 256) ws[i] = w1[i];
    __syncthreads();
    int lane = threadIdx.x & 31, wid = threadIdx.x >> 5;
    int n = blockIdx.x * 8 + wid;
    const float* xr = x + (long long)n * DIM_IN;
    float x0 = xr[lane], x1 = xr[32 + lane], x2 = xr[64 + lane], x3 = xr[96 + lane];
    float acc0 = 0.f, acc1 = 0.f;
    #pragma unroll
    for (int k = 0; k < 32; k++) {
        acc0 += __shfl_sync(FULLMASK, x0, k) * ws[k * 32 + lane];
        acc1 += __shfl_sync(FULLMASK, x1, k) * ws[(32 + k) * 32 + lane];
    }
    #pragma unroll
    for (int k = 0; k < 32; k++) {
        acc0 += __shfl_sync(FULLMASK, x2, k) * ws[(64 + k) * 32 + lane];
        acc1 += __shfl_sync(FULLMASK, x3, k) * ws[(96 + k) * 32 + lane];
    }
    g_xp[n * 32 + lane] = acc0 + acc1;
}

// ---------------- aggregation: t = bn_a*(self + sum_nb) + (deg+1)*bn_b -----
template <bool HAS_BN>
__global__ void __launch_bounds__(256) agg_kernel(
    const float* __restrict__ xin, float* __restrict__ tout, int sl,
    const float* __restrict__ gamma, const float* __restrict__ beta)
{
    __shared__ float sa[32], sb[32];
    if (HAS_BN) {
        if (threadIdx.x < 32) {
            float s = g_stats[sl * 64 + threadIdx.x];
            float q = g_stats[sl * 64 + 32 + threadIdx.x];
            const float invn = 1.f / (float)N_NODES;
            float m = s * invn;
            float vv = fmaxf(q * invn - m * m, 0.f);
            float a = gamma[threadIdx.x] * rsqrtf(vv + BN_EPS);
            sa[threadIdx.x] = a;
            sb[threadIdx.x] = beta[threadIdx.x] - a * m;
        }
        __syncthreads();
    }
    int lane = threadIdx.x & 31, wid = threadIdx.x >> 5;
    int n = blockIdx.x * 8 + wid;
    int start = g_rowptr[n], end = g_rowptr[n + 1];

    float a0 = xin[n * 32 + lane], a1 = 0.f, a2 = 0.f, a3 = 0.f;

    for (int b0 = start; b0 < end; b0 += 32) {
        int nrem = end - b0;                       // >= 1
        int li = (lane < nrem) ? lane : 0;
        int idx = g_col[b0 + li];
        #pragma unroll
        for (int k = 0; k < 32; k += 8) {
            if (nrem > k) {
                int j0 = __shfl_sync(FULLMASK, idx, k + 0);
                int j1 = __shfl_sync(FULLMASK, idx, k + 1);
                int j2 = __shfl_sync(FULLMASK, idx, k + 2);
                int j3 = __shfl_sync(FULLMASK, idx, k + 3);
                int j4 = __shfl_sync(FULLMASK, idx, k + 4);
                int j5 = __shfl_sync(FULLMASK, idx, k + 5);
                int j6 = __shfl_sync(FULLMASK, idx, k + 6);
                int j7 = __shfl_sync(FULLMASK, idx, k + 7);
                float v0 = xin[j0 * 32 + lane];
                float v1 = xin[j1 * 32 + lane];
                float v2 = xin[j2 * 32 + lane];
                float v3 = xin[j3 * 32 + lane];
                float v4 = xin[j4 * 32 + lane];
                float v5 = xin[j5 * 32 + lane];
                float v6 = xin[j6 * 32 + lane];
                float v7 = xin[j7 * 32 + lane];
                a0 += v0;                               // k < nrem guaranteed
                if (k + 1 < nrem) a1 += v1;
                if (k + 2 < nrem) a2 += v2;
                if (k + 3 < nrem) a3 += v3;
                if (k + 4 < nrem) a0 += v4;
                if (k + 5 < nrem) a1 += v5;
                if (k + 6 < nrem) a2 += v6;
                if (k + 7 < nrem) a3 += v7;
            }
        }
    }
    float acc = (a0 + a1) + (a2 + a3);
    float t;
    if (HAS_BN) t = sa[lane] * acc + (float)(end - start + 1) * sb[lane];
    else        t = acc;
    tout[n * 32 + lane] = t;
}

// ---------------- GEMM-tiled MLP: h2 = relu(relu(t@w1+b1)@w2+b2) + stats ---
template <bool APPLY_W1>
__global__ void __launch_bounds__(256) mlp_kernel(
    const float* __restrict__ tin, float* __restrict__ outp,
    const float* __restrict__ w1, const float* __restrict__ b1,
    const float* __restrict__ w2, const float* __restrict__ b2, int sl)
{
    __shared__ __align__(16) float s_buf[32 * 132];    // [k][node], stride 132
    __shared__ __align__(16) float s_w1[1024];
    __shared__ __align__(16) float s_w2[1024];
    __shared__ float s_b1[32], s_b2[32], s_sum[32], s_sq[32];

    int tid = threadIdx.x, lane = tid & 31, wrp = tid >> 5;
    int n0 = blockIdx.x * 128;

    if (APPLY_W1) for (int i = tid; i < 1024; i += 256) s_w1[i] = w1[i];
    for (int i = tid; i < 1024; i += 256) s_w2[i] = w2[i];
    if (tid < 32) { s_b1[tid] = b1[tid]; s_b2[tid] = b2[tid]; s_sum[tid] = 0.f; s_sq[tid] = 0.f; }

    // load t transposed: s_buf[f*132 + l] = t[n0+l][f]
    #pragma unroll
    for (int r = wrp; r < 128; r += 8) {
        int nn = n0 + r;
        float v = (nn < N_NODES) ? tin[nn * 32 + lane] : 0.f;
        s_buf[lane * 132 + r] = v;
    }
    __syncthreads();

    int nb = (tid & 31) * 4;      // node sub-tile base (0..124)
    int fb = (tid >> 5) * 4;      // feature sub-tile base (0..28)

    float h[16];
    if (APPLY_W1) {
        #pragma unroll
        for (int i = 0; i < 16; i++) h[i] = 0.f;
        #pragma unroll
        for (int k = 0; k < 32; k++) {
            float4 tv = *(const float4*)&s_buf[k * 132 + nb];
            float4 wv = *(const float4*)&s_w1[k * 32 + fb];
            h[0]  += tv.x * wv.x; h[1]  += tv.x * wv.y; h[2]  += tv.x * wv.z; h[3]  += tv.x * wv.w;
            h[4]  += tv.y * wv.x; h[5]  += tv.y * wv.y; h[6]  += tv.y * wv.z; h[7]  += tv.y * wv.w;
            h[8]  += tv.z * wv.x; h[9]  += tv.z * wv.y; h[10] += tv.z * wv.z; h[11] += tv.z * wv.w;
            h[12] += tv.w * wv.x; h[13] += tv.w * wv.y; h[14] += tv.w * wv.z; h[15] += tv.w * wv.w;
        }
        #pragma unroll
        for (int ni = 0; ni < 4; ni++)
            #pragma unroll
            for (int fi = 0; fi < 4; fi++)
                h[ni * 4 + fi] = fmaxf(h[ni * 4 + fi] + s_b1[fb + fi], 0.f);
    } else {
        #pragma unroll
        for (int ni = 0; ni < 4; ni++)
            #pragma unroll
            for (int fi = 0; fi < 4; fi++)
                h[ni * 4 + fi] = fmaxf(s_buf[(fb + fi) * 132 + nb + ni] + s_b1[fb + fi], 0.f);
    }
    __syncthreads();
    // store h1 transposed-consistent: s_buf[f][node]
    #pragma unroll
    for (int fi = 0; fi < 4; fi++) {
        float4 hv = make_float4(h[0 * 4 + fi], h[1 * 4 + fi], h[2 * 4 + fi], h[3 * 4 + fi]);
        *(float4*)&s_buf[(fb + fi) * 132 + nb] = hv;
    }
    __syncthreads();

    // GEMM2
    #pragma unroll
    for (int i = 0; i < 16; i++) h[i] = 0.f;
    #pragma unroll
    for (int k = 0; k < 32; k++) {
        float4 tv = *(const float4*)&s_buf[k * 132 + nb];
        float4 wv = *(const float4*)&s_w2[k * 32 + fb];
        h[0]  += tv.x * wv.x; h[1]  += tv.x * wv.y; h[2]  += tv.x * wv.z; h[3]  += tv.x * wv.w;
        h[4]  += tv.y * wv.x; h[5]  += tv.y * wv.y; h[6]  += tv.y * wv.z; h[7]  += tv.y * wv.w;
        h[8]  += tv.z * wv.x; h[9]  += tv.z * wv.y; h[10] += tv.z * wv.z; h[11] += tv.z * wv.w;
        h[12] += tv.w * wv.x; h[13] += tv.w * wv.y; h[14] += tv.w * wv.z; h[15] += tv.w * wv.w;
    }
    #pragma unroll
    for (int ni = 0; ni < 4; ni++)
        #pragma unroll
        for (int fi = 0; fi < 4; fi++)
            h[ni * 4 + fi] = fmaxf(h[ni * 4 + fi] + s_b2[fb + fi], 0.f);

    // BN stats (mask tail nodes)
    #pragma unroll
    for (int fi = 0; fi < 4; fi++) {
        float p = 0.f, q = 0.f;
        #pragma unroll
        for (int ni = 0; ni < 4; ni++) {
            float v = ((n0 + nb + ni) < N_NODES) ? h[ni * 4 + fi] : 0.f;
            p += v; q += v * v;
        }
        #pragma unroll
        for (int off = 16; off; off >>= 1) {
            p += __shfl_down_sync(FULLMASK, p, off);
            q += __shfl_down_sync(FULLMASK, q, off);
        }
        if (lane == 0) { atomicAdd(&s_sum[fb + fi], p); atomicAdd(&s_sq[fb + fi], q); }
    }
    __syncthreads();

    // stage output node-major (stride 33) then coalesced global write
    #pragma unroll
    for (int ni = 0; ni < 4; ni++)
        #pragma unroll
        for (int fi = 0; fi < 4; fi++)
            s_buf[(nb + ni) * 33 + fb + fi] = h[ni * 4 + fi];
    __syncthreads();
    #pragma unroll
    for (int r = wrp; r < 128; r += 8) {
        int nn = n0 + r;
        if (nn < N_NODES) outp[nn * 32 + lane] = s_buf[r * 33 + lane];
    }
    if (tid < 32)       atomicAdd(&g_stats[sl * 64 + tid], s_sum[tid]);
    else if (tid < 64)  atomicAdd(&g_stats[sl * 64 + tid], s_sq[tid - 32]);
}

// ---------------- last decoder MLP: 32 -> 32 -> 128, ReLU ------------------
__global__ void __launch_bounds__(256) mlp_last_kernel(
    const float* __restrict__ tin, float* __restrict__ outp,
    const float* __restrict__ w1, const float* __restrict__ b1,
    const float* __restrict__ w2L, const float* __restrict__ b2L)
{
    __shared__ float wLs[HID * DIM_IN];
    for (int i = threadIdx.x; i < HID * DIM_IN; i += 256) wLs[i] = w2L[i];
    int lane = threadIdx.x & 31, wid = threadIdx.x >> 5;
    int n = blockIdx.x * 8 + wid;

    float rw1[32];
    #pragma unroll
    for (int k = 0; k < 32; k++) rw1[k] = w1[k * 32 + lane];
    float rb1 = b1[lane];
    __syncthreads();

    float t = tin[n * 32 + lane];
    float h1 = rb1;
    #pragma unroll
    for (int k = 0; k < 32; k++) h1 += __shfl_sync(FULLMASK, t, k) * rw1[k];
    h1 = fmaxf(h1, 0.f);

    float o0 = b2L[lane], o1 = b2L[32 + lane], o2 = b2L[64 + lane], o3 = b2L[96 + lane];
    #pragma unroll
    for (int k = 0; k < 32; k++) {
        float hk = __shfl_sync(FULLMASK, h1, k);
        const float* wr = &wLs[k * 128];
        o0 += hk * wr[lane];
        o1 += hk * wr[32 + lane];
        o2 += hk * wr[64 + lane];
        o3 += hk * wr[96 + lane];
    }
    float* orow = outp + (long long)n * 128;
    orow[lane]      = fmaxf(o0, 0.f);
    orow[32 + lane] = fmaxf(o1, 0.f);
    orow[64 + lane] = fmaxf(o2, 0.f);
    orow[96 + lane] = fmaxf(o3, 0.f);
}

// ---------------- BN apply (final encoder output only) ---------------------
__global__ void __launch_bounds__(256) bn_out_kernel(
    const float* __restrict__ pre, float* __restrict__ outp, int sl,
    const float* __restrict__ gamma, const float* __restrict__ beta)
{
    __shared__ float sa[32], sb[32];
    if (threadIdx.x < 32) {
        float s = g_stats[sl * 64 + threadIdx.x];
        float q = g_stats[sl * 64 + 32 + threadIdx.x];
        const float invn = 1.f / (float)N_NODES;
        float m = s * invn;
        float v = fmaxf(q * invn - m * m, 0.f);
        float a = gamma[threadIdx.x] * rsqrtf(v + BN_EPS);
        sa[threadIdx.x] = a;
        sb[threadIdx.x] = beta[threadIdx.x] - a * m;
    }
    __syncthreads();
    int i = blockIdx.x * 256 + threadIdx.x;     // float4 index; exact coverage
    int f0 = (i & 7) * 4;
    float4 v4 = ((const float4*)pre)[i];
    v4.x = sa[f0]     * v4.x + sb[f0];
    v4.y = sa[f0 + 1] * v4.y + sb[f0 + 1];
    v4.z = sa[f0 + 2] * v4.z + sb[f0 + 2];
    v4.w = sa[f0 + 3] * v4.w + sb[f0 + 3];
    ((float4*)outp)[i] = v4;
}

// ---------------- pool of post-BN layer rep (affine of raw pool) -----------
__global__ void __launch_bounds__(256) pool_kernel(
    const float* __restrict__ src, float* __restrict__ dst, int layer, int sl,
    const float* __restrict__ gamma, const float* __restrict__ beta)
{
    __shared__ float sa[32], sb2[32];
    __shared__ float sp[256];
    int tid = threadIdx.x;
    if (tid < 32) {
        float s = g_stats[sl * 64 + tid];
        float q = g_stats[sl * 64 + 32 + tid];
        const float invn = 1.f / (float)N_NODES;
        float m = s * invn;
        float v = fmaxf(q * invn - m * m, 0.f);
        float a = gamma[tid] * rsqrtf(v + BN_EPS);
        sa[tid] = a;
        sb2[tid] = beta[tid] - a * m;
    }
    __syncthreads();
    int g = blockIdx.x;
    int s = g_goff[g], e = g_goff[g + 1];
    int f = tid & 31, sub = tid >> 5;
    float p = 0.f;
    for (int r = s + sub; r < e; r += 8) p += src[r * 32 + f];
    sp[tid] = p;
    __syncthreads();
    if (tid < 32) {
        float t = sp[f];
        #pragma unroll
        for (int j = 1; j < 8; j++) t += sp[j * 32 + f];
        dst[g * (5 * HID) + layer * HID + f] = sa[f] * t + (float)(e - s) * sb2[f];
    }
}

// ---------------- launch ---------------------------------------------------
extern "C" void kernel_launch(void* const* d_in, const int* in_sizes, int n_in,
                              void* d_out, int out_size) {
    const float* x        = (const float*)d_in[0];
    const int*   ei       = (const int*)d_in[1];
    const int*   batch    = (const int*)d_in[2];
    const float* e0_w1    = (const float*)d_in[3];
    const float* e0_b1    = (const float*)d_in[4];
    const float* e0_w2    = (const float*)d_in[5];
    const float* e0_b2    = (const float*)d_in[6];
    const float* enc_w1   = (const float*)d_in[7];
    const float* enc_b1   = (const float*)d_in[8];
    const float* enc_w2   = (const float*)d_in[9];
    const float* enc_b2   = (const float*)d_in[10];
    const float* enc_gamma= (const float*)d_in[11];
    const float* enc_beta = (const float*)d_in[12];
    const float* dec_w1   = (const float*)d_in[13];
    const float* dec_b1   = (const float*)d_in[14];
    const float* dec_w2   = (const float*)d_in[15];
    const float* dec_b2   = (const float*)d_in[16];
    const float* dec_w2_last = (const float*)d_in[17];
    const float* dec_b2_last = (const float*)d_in[18];
    const float* dec_gamma= (const float*)d_in[19];
    const float* dec_beta = (const float*)d_in[20];
    float* out = (float*)d_out;

    const int* srcp = ei;
    const int* dstp = ei + N_EDGES;

    float *pA, *pT, *pXP;
    cudaGetSymbolAddress((void**)&pA,  g_bufA);
    cudaGetSymbolAddress((void**)&pT,  g_bufT);
    cudaGetSymbolAddress((void**)&pXP, g_xp);

    // CSR build + graph offsets (once per launch)
    init_kernel<<<782, 256>>>();
    offsets_kernel<<<3, 256>>>(batch);
    hist_kernel<<<25000, 256>>>(dstp);
    scan_block_kernel<<<SCAN_BLOCKS, 1024>>>();
    scan_tops_kernel<<<1, 256>>>();
    scan_add_kernel<<<SCAN_BLOCKS, 1024>>>();
    permute_kernel<<<25000, 256>>>(srcp, dstp);

    // layer-0 projection (linearity: aggregate 32-dim, not 128-dim)
    proj_kernel<<<25000, 256>>>(x, e0_w1);

    // ----- encoder (BN folded into next layer's aggregation + pool) -----
    agg_kernel<false><<<25000, 256>>>(pXP, pT, 0, nullptr, nullptr);
    mlp_kernel<false><<<1563, 256>>>(pT, pA, nullptr, e0_b1, e0_w2, e0_b2, 0);
    pool_kernel<<<N_GRAPHS, 256>>>(pA, out + GLOB_OFF, 0, 0, enc_gamma, enc_beta);
    for (int L = 1; L < 5; L++) {
        agg_kernel<true><<<25000, 256>>>(pA, pT, L - 1,
            enc_gamma + (L - 1) * 32, enc_beta + (L - 1) * 32);
        mlp_kernel<true><<<1563, 256>>>(pT, pA,
            enc_w1 + (L - 1) * 1024, enc_b1 + (L - 1) * 32,
            enc_w2 + (L - 1) * 1024, enc_b2 + (L - 1) * 32, L);
        pool_kernel<<<N_GRAPHS, 256>>>(pA, out + GLOB_OFF, L, L,
            enc_gamma + L * 32, enc_beta + L * 32);
    }
    bn_out_kernel<<<6250, 256>>>(pA, out + ENC_OFF, 4, enc_gamma + 4 * 32, enc_beta + 4 * 32);

    // ----- decoder -----
    for (int L = 0; L < 4; L++) {
        const float* gI = (L == 0) ? (enc_gamma + 4 * 32) : (dec_gamma + (L - 1) * 32);
        const float* bI = (L == 0) ? (enc_beta  + 4 * 32) : (dec_beta  + (L - 1) * 32);
        int slin = (L == 0) ? 4 : (4 + L);
        agg_kernel<true><<<25000, 256>>>(pA, pT, slin, gI, bI);
        mlp_kernel<true><<<1563, 256>>>(pT, pA,
            dec_w1 + L * 1024, dec_b1 + L * 32,
            dec_w2 + L * 1024, dec_b2 + L * 32, 5 + L);
    }
    agg_kernel<true><<<25000, 256>>>(pA, pT, 8, dec_gamma + 3 * 32, dec_beta + 3 * 32);
    mlp_last_kernel<<<25000, 256>>>(pT, out + DEC_OFF,
        dec_w1 + 4 * 1024, dec_b1 + 4 * 32, dec_w2_last, dec_b2_last);
}

// round 8
// speedup vs baseline: 1.5362x; 1.1591x over previous
#include <cuda_runtime.h>
#include <cuda_bf16.h>

#define N_NODES   200000
#define N_EDGES   6400000
#define N_GRAPHS  512
#define DIM_IN    128
#define HID       32
#define BN_EPS    1e-5f

#define ENC_OFF   0
#define DEC_OFF   (N_NODES * HID)                     // 6,400,000
#define GLOB_OFF  (N_NODES * HID + N_NODES * DIM_IN)  // 32,000,000

#define FULLMASK  0xffffffffu
#define SCAN_BLOCKS 196

// ---------------- scratch (device globals; no cudaMalloc allowed) ----------
__device__ int   g_cnt[N_NODES];
__device__ int   g_rowptr[N_NODES + 1];
__device__ int   g_cursor[N_NODES];
__device__ int   g_col[N_EDGES];
__device__ int   g_bsum[SCAN_BLOCKS];
__device__ int   g_boff[SCAN_BLOCKS];
__device__ int   g_goff[N_GRAPHS + 1];
__device__ float g_stats[10 * 64];                    // per layer: sum[32], sumsq[32]
__device__ __align__(16) float g_xp[N_NODES * HID];   // projected layer-0 input
__device__ __align__(16) float g_bufA[N_NODES * HID]; // ping
__device__ __align__(16) float g_bufC[N_NODES * HID]; // pong

// ---------------- setup kernels --------------------------------------------
__global__ void init_kernel() {
    int i = blockIdx.x * 256 + threadIdx.x;
    if (i < N_NODES) g_cnt[i] = 0;
    if (i < 10 * 64) g_stats[i] = 0.f;
}

__global__ void offsets_kernel(const int* __restrict__ batch) {
    int g = blockIdx.x * 256 + threadIdx.x;
    if (g > N_GRAPHS) return;
    if (g == N_GRAPHS) { g_goff[g] = N_NODES; return; }
    int lo = 0, hi = N_NODES;
    while (lo < hi) {
        int mid = (lo + hi) >> 1;
        if (batch[mid] < g) lo = mid + 1; else hi = mid;
    }
    g_goff[g] = lo;
}

__global__ void hist_kernel(const int* __restrict__ dst) {
    int e = blockIdx.x * 256 + threadIdx.x;   // exact: 25000*256 == N_EDGES
    atomicAdd(&g_cnt[dst[e]], 1);
}

// --- 3-phase exclusive scan of g_cnt -> g_rowptr / g_cursor ----------------
__global__ void scan_block_kernel() {      // SCAN_BLOCKS x 1024
    __shared__ int wtot[32];
    int tid = threadIdx.x, lane = tid & 31, wid = tid >> 5;
    int i = blockIdx.x * 1024 + tid;
    int v = (i < N_NODES) ? g_cnt[i] : 0;
    int incl = v;
    #pragma unroll
    for (int off = 1; off < 32; off <<= 1) {
        int t = __shfl_up_sync(FULLMASK, incl, off);
        if (lane >= off) incl += t;
    }
    if (lane == 31) wtot[wid] = incl;
    __syncthreads();
    if (wid == 0) {
        int wv = wtot[lane];
        #pragma unroll
        for (int off = 1; off < 32; off <<= 1) {
            int t = __shfl_up_sync(FULLMASK, wv, off);
            if (lane >= off) wv += t;
        }
        wtot[lane] = wv;
    }
    __syncthreads();
    int excl = (wid ? wtot[wid - 1] : 0) + incl - v;
    if (i < N_NODES) g_rowptr[i] = excl;
    if (tid == 1023) g_bsum[blockIdx.x] = wtot[31];
}

__global__ void scan_tops_kernel() {       // 1 x 256
    __shared__ int wt[8];
    int tid = threadIdx.x, lane = tid & 31, wid = tid >> 5;
    int v = (tid < SCAN_BLOCKS) ? g_bsum[tid] : 0;
    int incl = v;
    #pragma unroll
    for (int off = 1; off < 32; off <<= 1) {
        int t = __shfl_up_sync(FULLMASK, incl, off);
        if (lane >= off) incl += t;
    }
    if (lane == 31) wt[wid] = incl;
    __syncthreads();
    if (wid == 0) {
        int wv = (lane < 8) ? wt[lane] : 0;
        #pragma unroll
        for (int off = 1; off < 32; off <<= 1) {
            int t = __shfl_up_sync(FULLMASK, wv, off);
            if (lane >= off) wv += t;
        }
        if (lane < 8) wt[lane] = wv;
    }
    __syncthreads();
    int excl = (wid ? wt[wid - 1] : 0) + incl - v;
    if (tid < SCAN_BLOCKS) g_boff[tid] = excl;
}

__global__ void scan_add_kernel() {        // SCAN_BLOCKS x 1024
    int i = blockIdx.x * 1024 + threadIdx.x;
    if (i < N_NODES) {
        int r = g_rowptr[i] + g_boff[blockIdx.x];
        g_rowptr[i] = r;
        g_cursor[i] = r;
    }
    if (i == 0) g_rowptr[N_NODES] = N_EDGES;
}

__global__ void permute_kernel(const int* __restrict__ src, const int* __restrict__ dst) {
    int e = blockIdx.x * 256 + threadIdx.x;
    int d = dst[e];
    int p = atomicAdd(&g_cursor[d], 1);
    g_col[p] = src[e];
}

// ---------------- projection: xp = x @ e0_w1 (128 -> 32) -------------------
__global__ void __launch_bounds__(256) proj_kernel(const float* __restrict__ x,
                                                   const float* __restrict__ w1) {
    __shared__ float ws[DIM_IN * HID];
    for (int i = threadIdx.x; i < DIM_IN * HID; i += 256) ws[i] = w1[i];
    __syncthreads();
    int lane = threadIdx.x & 31, wid = threadIdx.x >> 5;
    int n = blockIdx.x * 8 + wid;
    const float* xr = x + (long long)n * DIM_IN;
    float x0 = xr[lane], x1 = xr[32 + lane], x2 = xr[64 + lane], x3 = xr[96 + lane];
    float acc0 = 0.f, acc1 = 0.f;
    #pragma unroll
    for (int k = 0; k < 32; k++) {
        acc0 += __shfl_sync(FULLMASK, x0, k) * ws[k * 32 + lane];
        acc1 += __shfl_sync(FULLMASK, x1, k) * ws[(32 + k) * 32 + lane];
    }
    #pragma unroll
    for (int k = 0; k < 32; k++) {
        acc0 += __shfl_sync(FULLMASK, x2, k) * ws[(64 + k) * 32 + lane];
        acc1 += __shfl_sync(FULLMASK, x3, k) * ws[(96 + k) * 32 + lane];
    }
    g_xp[n * 32 + lane] = acc0 + acc1;
}

// ---------------- fused GIN: fp32 gather + BN-fold + MLP + stats -----------
// t = bn_a*(self + sum_nb) + (deg+1)*bn_b ; out = relu(relu(t@w1+b1)@w2+b2)
template <bool HAS_BN, bool APPLY_W1>
__global__ void __launch_bounds__(256) gin_fused_kernel(
    const float* __restrict__ xin, float* __restrict__ outp,
    const float* __restrict__ w1, const float* __restrict__ b1,
    const float* __restrict__ w2, const float* __restrict__ b2,
    int sl_in, const float* __restrict__ gamma, const float* __restrict__ beta,
    int sl_out)
{
    __shared__ float s_w1[1024], s_w2[1024];
    __shared__ float sa[32], sb[32], s_b1[32], s_b2[32], s_sum[32], s_sq[32];
    int tid = threadIdx.x, lane = tid & 31, wrp = tid >> 5;

    if (APPLY_W1) for (int i = tid; i < 1024; i += 256) s_w1[i] = w1[i];
    for (int i = tid; i < 1024; i += 256) s_w2[i] = w2[i];
    if (tid < 32) {
        s_b1[tid] = b1[tid]; s_b2[tid] = b2[tid];
        s_sum[tid] = 0.f; s_sq[tid] = 0.f;
        if (HAS_BN) {
            float s = g_stats[sl_in * 64 + tid];
            float q = g_stats[sl_in * 64 + 32 + tid];
            const float invn = 1.f / (float)N_NODES;
            float m = s * invn;
            float v = fmaxf(q * invn - m * m, 0.f);
            float a = gamma[tid] * rsqrtf(v + BN_EPS);
            sa[tid] = a;
            sb[tid] = beta[tid] - a * m;
        }
    }
    __syncthreads();

    int n = blockIdx.x * 8 + wrp;
    int start = g_rowptr[n], end = g_rowptr[n + 1];

    float a0 = xin[n * 32 + lane], a1 = 0.f, a2 = 0.f, a3 = 0.f;

    for (int b0 = start; b0 < end; b0 += 32) {
        int nrem = end - b0;                       // >= 1
        int li = (lane < nrem) ? lane : 0;
        int idx = g_col[b0 + li];
        #pragma unroll
        for (int k = 0; k < 32; k += 8) {
            if (nrem > k) {
                int j0 = __shfl_sync(FULLMASK, idx, k + 0);
                int j1 = __shfl_sync(FULLMASK, idx, k + 1);
                int j2 = __shfl_sync(FULLMASK, idx, k + 2);
                int j3 = __shfl_sync(FULLMASK, idx, k + 3);
                int j4 = __shfl_sync(FULLMASK, idx, k + 4);
                int j5 = __shfl_sync(FULLMASK, idx, k + 5);
                int j6 = __shfl_sync(FULLMASK, idx, k + 6);
                int j7 = __shfl_sync(FULLMASK, idx, k + 7);
                float v0 = xin[j0 * 32 + lane];
                float v1 = xin[j1 * 32 + lane];
                float v2 = xin[j2 * 32 + lane];
                float v3 = xin[j3 * 32 + lane];
                float v4 = xin[j4 * 32 + lane];
                float v5 = xin[j5 * 32 + lane];
                float v6 = xin[j6 * 32 + lane];
                float v7 = xin[j7 * 32 + lane];
                a0 += v0;                               // k < nrem guaranteed
                if (k + 1 < nrem) a1 += v1;
                if (k + 2 < nrem) a2 += v2;
                if (k + 3 < nrem) a3 += v3;
                if (k + 4 < nrem) a0 += v4;
                if (k + 5 < nrem) a1 += v5;
                if (k + 6 < nrem) a2 += v6;
                if (k + 7 < nrem) a3 += v7;
            }
        }
    }
    float t = (a0 + a1) + (a2 + a3);

    if (HAS_BN) t = sa[lane] * t + (float)(end - start + 1) * sb[lane];

    float h1;
    if (APPLY_W1) {
        h1 = s_b1[lane];
        #pragma unroll
        for (int k = 0; k < 32; k++) h1 += __shfl_sync(FULLMASK, t, k) * s_w1[k * 32 + lane];
    } else {
        h1 = t + s_b1[lane];
    }
    h1 = fmaxf(h1, 0.f);

    float h2 = s_b2[lane];
    #pragma unroll
    for (int k = 0; k < 32; k++) h2 += __shfl_sync(FULLMASK, h1, k) * s_w2[k * 32 + lane];
    h2 = fmaxf(h2, 0.f);

    outp[n * 32 + lane] = h2;

    atomicAdd(&s_sum[lane], h2);
    atomicAdd(&s_sq[lane], h2 * h2);
    __syncthreads();
    if (tid < 32)       atomicAdd(&g_stats[sl_out * 64 + tid], s_sum[tid]);
    else if (tid < 64)  atomicAdd(&g_stats[sl_out * 64 + tid], s_sq[tid - 32]);
}

// ---------------- final fused layer: gather + BN-fold + 32->32->128 --------
__global__ void __launch_bounds__(256) gin_last_fused_kernel(
    const float* __restrict__ xin, float* __restrict__ outp,
    const float* __restrict__ w1, const float* __restrict__ b1,
    const float* __restrict__ w2L, const float* __restrict__ b2L,
    int sl_in, const float* __restrict__ gamma, const float* __restrict__ beta)
{
    __shared__ float s_w1[1024];
    __shared__ float wLs[HID * DIM_IN];
    __shared__ float sa[32], sb[32], s_b1[32];
    int tid = threadIdx.x, lane = tid & 31, wrp = tid >> 5;

    for (int i = tid; i < 1024; i += 256) s_w1[i] = w1[i];
    for (int i = tid; i < HID * DIM_IN; i += 256) wLs[i] = w2L[i];
    if (tid < 32) {
        s_b1[tid] = b1[tid];
        float s = g_stats[sl_in * 64 + tid];
        float q = g_stats[sl_in * 64 + 32 + tid];
        const float invn = 1.f / (float)N_NODES;
        float m = s * invn;
        float v = fmaxf(q * invn - m * m, 0.f);
        float a = gamma[tid] * rsqrtf(v + BN_EPS);
        sa[tid] = a;
        sb[tid] = beta[tid] - a * m;
    }
    __syncthreads();

    int n = blockIdx.x * 8 + wrp;
    int start = g_rowptr[n], end = g_rowptr[n + 1];

    float a0 = xin[n * 32 + lane], a1 = 0.f, a2 = 0.f, a3 = 0.f;
    for (int b0 = start; b0 < end; b0 += 32) {
        int nrem = end - b0;
        int li = (lane < nrem) ? lane : 0;
        int idx = g_col[b0 + li];
        #pragma unroll
        for (int k = 0; k < 32; k += 8) {
            if (nrem > k) {
                int j0 = __shfl_sync(FULLMASK, idx, k + 0);
                int j1 = __shfl_sync(FULLMASK, idx, k + 1);
                int j2 = __shfl_sync(FULLMASK, idx, k + 2);
                int j3 = __shfl_sync(FULLMASK, idx, k + 3);
                int j4 = __shfl_sync(FULLMASK, idx, k + 4);
                int j5 = __shfl_sync(FULLMASK, idx, k + 5);
                int j6 = __shfl_sync(FULLMASK, idx, k + 6);
                int j7 = __shfl_sync(FULLMASK, idx, k + 7);
                float v0 = xin[j0 * 32 + lane];
                float v1 = xin[j1 * 32 + lane];
                float v2 = xin[j2 * 32 + lane];
                float v3 = xin[j3 * 32 + lane];
                float v4 = xin[j4 * 32 + lane];
                float v5 = xin[j5 * 32 + lane];
                float v6 = xin[j6 * 32 + lane];
                float v7 = xin[j7 * 32 + lane];
                a0 += v0;
                if (k + 1 < nrem) a1 += v1;
                if (k + 2 < nrem) a2 += v2;
                if (k + 3 < nrem) a3 += v3;
                if (k + 4 < nrem) a0 += v4;
                if (k + 5 < nrem) a1 += v5;
                if (k + 6 < nrem) a2 += v6;
                if (k + 7 < nrem) a3 += v7;
            }
        }
    }
    float t = (a0 + a1) + (a2 + a3);
    t = sa[lane] * t + (float)(end - start + 1) * sb[lane];

    float h1 = s_b1[lane];
    #pragma unroll
    for (int k = 0; k < 32; k++) h1 += __shfl_sync(FULLMASK, t, k) * s_w1[k * 32 + lane];
    h1 = fmaxf(h1, 0.f);

    float o0 = b2L[lane], o1 = b2L[32 + lane], o2 = b2L[64 + lane], o3 = b2L[96 + lane];
    #pragma unroll
    for (int k = 0; k < 32; k++) {
        float hk = __shfl_sync(FULLMASK, h1, k);
        const float* wr = &wLs[k * 128];
        o0 += hk * wr[lane];
        o1 += hk * wr[32 + lane];
        o2 += hk * wr[64 + lane];
        o3 += hk * wr[96 + lane];
    }
    float* orow = outp + (long long)n * 128;
    orow[lane]      = fmaxf(o0, 0.f);
    orow[32 + lane] = fmaxf(o1, 0.f);
    orow[64 + lane] = fmaxf(o2, 0.f);
    orow[96 + lane] = fmaxf(o3, 0.f);
}

// ---------------- BN apply (final encoder output only) ---------------------
__global__ void __launch_bounds__(256) bn_out_kernel(
    const float* __restrict__ pre, float* __restrict__ outp, int sl,
    const float* __restrict__ gamma, const float* __restrict__ beta)
{
    __shared__ float sa[32], sb[32];
    if (threadIdx.x < 32) {
        float s = g_stats[sl * 64 + threadIdx.x];
        float q = g_stats[sl * 64 + 32 + threadIdx.x];
        const float invn = 1.f / (float)N_NODES;
        float m = s * invn;
        float v = fmaxf(q * invn - m * m, 0.f);
        float a = gamma[threadIdx.x] * rsqrtf(v + BN_EPS);
        sa[threadIdx.x] = a;
        sb[threadIdx.x] = beta[threadIdx.x] - a * m;
    }
    __syncthreads();
    int i = blockIdx.x * 256 + threadIdx.x;     // float4 index; exact coverage
    int f0 = (i & 7) * 4;
    float4 v4 = ((const float4*)pre)[i];
    v4.x = sa[f0]     * v4.x + sb[f0];
    v4.y = sa[f0 + 1] * v4.y + sb[f0 + 1];
    v4.z = sa[f0 + 2] * v4.z + sb[f0 + 2];
    v4.w = sa[f0 + 3] * v4.w + sb[f0 + 3];
    ((float4*)outp)[i] = v4;
}

// ---------------- pool of post-BN layer rep (affine of raw pool) -----------
__global__ void __launch_bounds__(256) pool_kernel(
    const float* __restrict__ src, float* __restrict__ dst, int layer, int sl,
    const float* __restrict__ gamma, const float* __restrict__ beta)
{
    __shared__ float sa[32], sb2[32];
    __shared__ float sp[256];
    int tid = threadIdx.x;
    if (tid < 32) {
        float s = g_stats[sl * 64 + tid];
        float q = g_stats[sl * 64 + 32 + tid];
        const float invn = 1.f / (float)N_NODES;
        float m = s * invn;
        float v = fmaxf(q * invn - m * m, 0.f);
        float a = gamma[tid] * rsqrtf(v + BN_EPS);
        sa[tid] = a;
        sb2[tid] = beta[tid] - a * m;
    }
    __syncthreads();
    int g = blockIdx.x;
    int s = g_goff[g], e = g_goff[g + 1];
    int f = tid & 31, sub = tid >> 5;
    float p = 0.f;
    for (int r = s + sub; r < e; r += 8) p += src[r * 32 + f];
    sp[tid] = p;
    __syncthreads();
    if (tid < 32) {
        float t = sp[f];
        #pragma unroll
        for (int j = 1; j < 8; j++) t += sp[j * 32 + f];
        dst[g * (5 * HID) + layer * HID + f] = sa[f] * t + (float)(e - s) * sb2[f];
    }
}

// ---------------- launch ---------------------------------------------------
extern "C" void kernel_launch(void* const* d_in, const int* in_sizes, int n_in,
                              void* d_out, int out_size) {
    const float* x        = (const float*)d_in[0];
    const int*   ei       = (const int*)d_in[1];
    const int*   batch    = (const int*)d_in[2];
    const float* e0_w1    = (const float*)d_in[3];
    const float* e0_b1    = (const float*)d_in[4];
    const float* e0_w2    = (const float*)d_in[5];
    const float* e0_b2    = (const float*)d_in[6];
    const float* enc_w1   = (const float*)d_in[7];
    const float* enc_b1   = (const float*)d_in[8];
    const float* enc_w2   = (const float*)d_in[9];
    const float* enc_b2   = (const float*)d_in[10];
    const float* enc_gamma= (const float*)d_in[11];
    const float* enc_beta = (const float*)d_in[12];
    const float* dec_w1   = (const float*)d_in[13];
    const float* dec_b1   = (const float*)d_in[14];
    const float* dec_w2   = (const float*)d_in[15];
    const float* dec_b2   = (const float*)d_in[16];
    const float* dec_w2_last = (const float*)d_in[17];
    const float* dec_b2_last = (const float*)d_in[18];
    const float* dec_gamma= (const float*)d_in[19];
    const float* dec_beta = (const float*)d_in[20];
    float* out = (float*)d_out;

    const int* srcp = ei;
    const int* dstp = ei + N_EDGES;

    float *pA, *pC, *pXP;
    cudaGetSymbolAddress((void**)&pA,  g_bufA);
    cudaGetSymbolAddress((void**)&pC,  g_bufC);
    cudaGetSymbolAddress((void**)&pXP, g_xp);

    // CSR build + projection
    init_kernel<<<782, 256>>>();
    hist_kernel<<<25000, 256>>>(dstp);
    scan_block_kernel<<<SCAN_BLOCKS, 1024>>>();
    proj_kernel<<<25000, 256>>>(x, e0_w1);       // launch index 3 (ncu capture slot)
    scan_tops_kernel<<<1, 256>>>();
    scan_add_kernel<<<SCAN_BLOCKS, 1024>>>();
    offsets_kernel<<<3, 256>>>(batch);
    permute_kernel<<<25000, 256>>>(srcp, dstp);

    float* cur = pXP;
    float* nxt = pA;
    float* alt = pC;

    // ----- encoder (BN folded into next layer's aggregation + pool) -----
    gin_fused_kernel<false, false><<<25000, 256>>>(cur, nxt, nullptr,
        e0_b1, e0_w2, e0_b2, 0, nullptr, nullptr, 0);
    cur = nxt; nxt = alt; alt = cur;   // cur=A, nxt=C
    pool_kernel<<<N_GRAPHS, 256>>>(cur, out + GLOB_OFF, 0, 0, enc_gamma, enc_beta);
    for (int L = 1; L < 5; L++) {
        gin_fused_kernel<true, true><<<25000, 256>>>(cur, nxt,
            enc_w1 + (L - 1) * 1024, enc_b1 + (L - 1) * 32,
            enc_w2 + (L - 1) * 1024, enc_b2 + (L - 1) * 32,
            L - 1, enc_gamma + (L - 1) * 32, enc_beta + (L - 1) * 32, L);
        { float* t = cur; cur = nxt; nxt = t; }
        pool_kernel<<<N_GRAPHS, 256>>>(cur, out + GLOB_OFF, L, L,
            enc_gamma + L * 32, enc_beta + L * 32);
    }
    bn_out_kernel<<<6250, 256>>>(cur, out + ENC_OFF, 4, enc_gamma + 4 * 32, enc_beta + 4 * 32);

    // ----- decoder -----
    for (int L = 0; L < 4; L++) {
        const float* gI = (L == 0) ? (enc_gamma + 4 * 32) : (dec_gamma + (L - 1) * 32);
        const float* bI = (L == 0) ? (enc_beta  + 4 * 32) : (dec_beta  + (L - 1) * 32);
        int slin = (L == 0) ? 4 : (4 + L);
        gin_fused_kernel<true, true><<<25000, 256>>>(cur, nxt,
            dec_w1 + L * 1024, dec_b1 + L * 32,
            dec_w2 + L * 1024, dec_b2 + L * 32,
            slin, gI, bI, 5 + L);
        { float* t = cur; cur = nxt; nxt = t; }
    }
    gin_last_fused_kernel<<<25000, 256>>>(cur, out + DEC_OFF,
        dec_w1 + 4 * 1024, dec_b1 + 4 * 32, dec_w2_last, dec_b2_last,
        8, dec_gamma + 3 * 32, dec_beta + 3 * 32);
}

// round 9
// speedup vs baseline: 1.7068x; 1.1111x over previous
#include <cuda_runtime.h>
#include <cuda_bf16.h>

#define N_NODES   200000
#define N_EDGES   6400000
#define N_GRAPHS  512
#define DIM_IN    128
#define HID       32
#define BN_EPS    1e-5f

#define ENC_OFF   0
#define DEC_OFF   (N_NODES * HID)                     // 6,400,000
#define GLOB_OFF  (N_NODES * HID + N_NODES * DIM_IN)  // 32,000,000

#define FULLMASK  0xffffffffu
#define SCAN_BLOCKS 196

// ---------------- scratch (device globals; no cudaMalloc allowed) ----------
__device__ int   g_cnt[N_NODES];
__device__ int   g_rowptr[N_NODES + 1];
__device__ int   g_cursor[N_NODES];
__device__ int   g_col[N_EDGES];
__device__ int   g_bsum[SCAN_BLOCKS];
__device__ int   g_boff[SCAN_BLOCKS];
__device__ int   g_goff[N_GRAPHS + 1];
__device__ float g_stats[10 * 64];                    // per layer: sum[32], sumsq[32]
__device__ __align__(16) float g_xp[N_NODES * HID];   // projected layer-0 input
__device__ __align__(16) float g_bufA[N_NODES * HID]; // ping
__device__ __align__(16) float g_bufC[N_NODES * HID]; // pong

// ---------------- setup kernels --------------------------------------------
__global__ void init_kernel() {
    int i = blockIdx.x * 256 + threadIdx.x;
    if (i < N_NODES) g_cnt[i] = 0;
    if (i < 10 * 64) g_stats[i] = 0.f;
}

__global__ void offsets_kernel(const int* __restrict__ batch) {
    int g = blockIdx.x * 256 + threadIdx.x;
    if (g > N_GRAPHS) return;
    if (g == N_GRAPHS) { g_goff[g] = N_NODES; return; }
    int lo = 0, hi = N_NODES;
    while (lo < hi) {
        int mid = (lo + hi) >> 1;
        if (batch[mid] < g) lo = mid + 1; else hi = mid;
    }
    g_goff[g] = lo;
}

__global__ void hist_kernel(const int* __restrict__ dst) {
    int e = blockIdx.x * 256 + threadIdx.x;   // exact: 25000*256 == N_EDGES
    atomicAdd(&g_cnt[dst[e]], 1);
}

// --- 3-phase exclusive scan of g_cnt -> g_rowptr / g_cursor ----------------
__global__ void scan_block_kernel() {      // SCAN_BLOCKS x 1024
    __shared__ int wtot[32];
    int tid = threadIdx.x, lane = tid & 31, wid = tid >> 5;
    int i = blockIdx.x * 1024 + tid;
    int v = (i < N_NODES) ? g_cnt[i] : 0;
    int incl = v;
    #pragma unroll
    for (int off = 1; off < 32; off <<= 1) {
        int t = __shfl_up_sync(FULLMASK, incl, off);
        if (lane >= off) incl += t;
    }
    if (lane == 31) wtot[wid] = incl;
    __syncthreads();
    if (wid == 0) {
        int wv = wtot[lane];
        #pragma unroll
        for (int off = 1; off < 32; off <<= 1) {
            int t = __shfl_up_sync(FULLMASK, wv, off);
            if (lane >= off) wv += t;
        }
        wtot[lane] = wv;
    }
    __syncthreads();
    int excl = (wid ? wtot[wid - 1] : 0) + incl - v;
    if (i < N_NODES) g_rowptr[i] = excl;
    if (tid == 1023) g_bsum[blockIdx.x] = wtot[31];
}

__global__ void scan_tops_kernel() {       // 1 x 256
    __shared__ int wt[8];
    int tid = threadIdx.x, lane = tid & 31, wid = tid >> 5;
    int v = (tid < SCAN_BLOCKS) ? g_bsum[tid] : 0;
    int incl = v;
    #pragma unroll
    for (int off = 1; off < 32; off <<= 1) {
        int t = __shfl_up_sync(FULLMASK, incl, off);
        if (lane >= off) incl += t;
    }
    if (lane == 31) wt[wid] = incl;
    __syncthreads();
    if (wid == 0) {
        int wv = (lane < 8) ? wt[lane] : 0;
        #pragma unroll
        for (int off = 1; off < 32; off <<= 1) {
            int t = __shfl_up_sync(FULLMASK, wv, off);
            if (lane >= off) wv += t;
        }
        if (lane < 8) wt[lane] = wv;
    }
    __syncthreads();
    int excl = (wid ? wt[wid - 1] : 0) + incl - v;
    if (tid < SCAN_BLOCKS) g_boff[tid] = excl;
}

__global__ void scan_add_kernel() {        // SCAN_BLOCKS x 1024
    int i = blockIdx.x * 1024 + threadIdx.x;
    if (i < N_NODES) {
        int r = g_rowptr[i] + g_boff[blockIdx.x];
        g_rowptr[i] = r;
        g_cursor[i] = r;
    }
    if (i == 0) g_rowptr[N_NODES] = N_EDGES;
}

__global__ void permute_kernel(const int* __restrict__ src, const int* __restrict__ dst) {
    int e = blockIdx.x * 256 + threadIdx.x;
    int d = dst[e];
    int p = atomicAdd(&g_cursor[d], 1);
    g_col[p] = src[e];
}

// ---------------- projection: xp = x @ e0_w1 (128 -> 32), GEMM-tiled -------
// dynamic smem: s_x[128k][132n] transposed tile + s_w[128][32]
#define PROJ_SMEM ((128 * 132 + 128 * 32) * 4)
__global__ void __launch_bounds__(256) proj_kernel(const float* __restrict__ x,
                                                   const float* __restrict__ w1) {
    extern __shared__ float sm[];
    float* s_x = sm;               // stride 132 over k-rows
    float* s_w = sm + 128 * 132;
    int tid = threadIdx.x, lane = tid & 31, wrp = tid >> 5;
    int n0 = blockIdx.x * 128;

    for (int i = tid; i < 4096; i += 256) s_w[i] = w1[i];
    #pragma unroll
    for (int r = wrp; r < 128; r += 8) {
        int nn = n0 + r;
        const float* xr = x + (long long)nn * 128;
        #pragma unroll
        for (int c0 = 0; c0 < 128; c0 += 32) {
            float v = (nn < N_NODES) ? xr[c0 + lane] : 0.f;
            s_x[(c0 + lane) * 132 + r] = v;
        }
    }
    __syncthreads();

    int nb = (tid & 31) * 4, fb = (tid >> 5) * 4;
    float h[16];
    #pragma unroll
    for (int i = 0; i < 16; i++) h[i] = 0.f;
    #pragma unroll 4
    for (int k = 0; k < 128; k++) {
        float4 xv = *(const float4*)&s_x[k * 132 + nb];
        float4 wv = *(const float4*)&s_w[k * 32 + fb];
        h[0]  += xv.x * wv.x; h[1]  += xv.x * wv.y; h[2]  += xv.x * wv.z; h[3]  += xv.x * wv.w;
        h[4]  += xv.y * wv.x; h[5]  += xv.y * wv.y; h[6]  += xv.y * wv.z; h[7]  += xv.y * wv.w;
        h[8]  += xv.z * wv.x; h[9]  += xv.z * wv.y; h[10] += xv.z * wv.z; h[11] += xv.z * wv.w;
        h[12] += xv.w * wv.x; h[13] += xv.w * wv.y; h[14] += xv.w * wv.z; h[15] += xv.w * wv.w;
    }
    __syncthreads();
    // stage node-major [128][33] then coalesced global write
    #pragma unroll
    for (int ni = 0; ni < 4; ni++)
        #pragma unroll
        for (int fi = 0; fi < 4; fi++)
            s_x[(nb + ni) * 33 + fb + fi] = h[ni * 4 + fi];
    __syncthreads();
    #pragma unroll
    for (int r = wrp; r < 128; r += 8) {
        int nn = n0 + r;
        if (nn < N_NODES) g_xp[nn * 32 + lane] = s_x[r * 33 + lane];
    }
}

// ---------------- vectorized gather helper ---------------------------------
// lane = (c = lane&7 feature-chunk, g = lane>>3 neighbor-subgroup)
// returns per-lane scalar t for feature f = lane (sum self + neighbors)
__device__ __forceinline__ float gather_sum(const float* __restrict__ xin,
                                            int n, int start, int end,
                                            int lane) {
    const float4* x4 = (const float4*)xin;
    int c = lane & 7;
    int g = lane >> 3;
    float4 acc = make_float4(0.f, 0.f, 0.f, 0.f);
    if (g == 0) acc = x4[n * 8 + c];                 // self term, counted once
    for (int b0 = start; b0 < end; b0 += 32) {
        int nrem = end - b0;                         // >= 1
        int li = (lane < nrem) ? lane : 0;
        int idx = g_col[b0 + li];
        #pragma unroll
        for (int k = 0; k < 32; k += 4) {
            if (k < nrem) {
                int j = __shfl_sync(FULLMASK, idx, k + g);
                float4 v = x4[j * 8 + c];
                if (k + g < nrem) {
                    acc.x += v.x; acc.y += v.y; acc.z += v.z; acc.w += v.w;
                }
            }
        }
    }
    // reduce across subgroups (xor 8, 16)
    acc.x += __shfl_xor_sync(FULLMASK, acc.x, 8);
    acc.y += __shfl_xor_sync(FULLMASK, acc.y, 8);
    acc.z += __shfl_xor_sync(FULLMASK, acc.z, 8);
    acc.w += __shfl_xor_sync(FULLMASK, acc.w, 8);
    acc.x += __shfl_xor_sync(FULLMASK, acc.x, 16);
    acc.y += __shfl_xor_sync(FULLMASK, acc.y, 16);
    acc.z += __shfl_xor_sync(FULLMASK, acc.z, 16);
    acc.w += __shfl_xor_sync(FULLMASK, acc.w, 16);
    // redistribute: feature f = lane lives in chunk lane>>2, component lane&3
    int srcl = lane >> 2;
    float tx = __shfl_sync(FULLMASK, acc.x, srcl);
    float ty = __shfl_sync(FULLMASK, acc.y, srcl);
    float tz = __shfl_sync(FULLMASK, acc.z, srcl);
    float tw = __shfl_sync(FULLMASK, acc.w, srcl);
    int comp = lane & 3;
    float t = (comp == 0) ? tx : (comp == 1) ? ty : (comp == 2) ? tz : tw;
    return t;
}

// ---------------- fused GIN: fp32 gather + BN-fold + MLP + stats -----------
// t = bn_a*(self + sum_nb) + (deg+1)*bn_b ; out = relu(relu(t@w1+b1)@w2+b2)
template <bool HAS_BN, bool APPLY_W1>
__global__ void __launch_bounds__(256) gin_fused_kernel(
    const float* __restrict__ xin, float* __restrict__ outp,
    const float* __restrict__ w1, const float* __restrict__ b1,
    const float* __restrict__ w2, const float* __restrict__ b2,
    int sl_in, const float* __restrict__ gamma, const float* __restrict__ beta,
    int sl_out)
{
    __shared__ float s_w1[1024], s_w2[1024];
    __shared__ float sa[32], sb[32], s_b1[32], s_b2[32], s_sum[32], s_sq[32];
    int tid = threadIdx.x, lane = tid & 31, wrp = tid >> 5;

    if (APPLY_W1) for (int i = tid; i < 1024; i += 256) s_w1[i] = w1[i];
    for (int i = tid; i < 1024; i += 256) s_w2[i] = w2[i];
    if (tid < 32) {
        s_b1[tid] = b1[tid]; s_b2[tid] = b2[tid];
        s_sum[tid] = 0.f; s_sq[tid] = 0.f;
        if (HAS_BN) {
            float s = g_stats[sl_in * 64 + tid];
            float q = g_stats[sl_in * 64 + 32 + tid];
            const float invn = 1.f / (float)N_NODES;
            float m = s * invn;
            float v = fmaxf(q * invn - m * m, 0.f);
            float a = gamma[tid] * rsqrtf(v + BN_EPS);
            sa[tid] = a;
            sb[tid] = beta[tid] - a * m;
        }
    }
    __syncthreads();

    int n = blockIdx.x * 8 + wrp;
    int start = g_rowptr[n], end = g_rowptr[n + 1];

    float t = gather_sum(xin, n, start, end, lane);

    if (HAS_BN) t = sa[lane] * t + (float)(end - start + 1) * sb[lane];

    float h1;
    if (APPLY_W1) {
        h1 = s_b1[lane];
        #pragma unroll
        for (int k = 0; k < 32; k++) h1 += __shfl_sync(FULLMASK, t, k) * s_w1[k * 32 + lane];
    } else {
        h1 = t + s_b1[lane];
    }
    h1 = fmaxf(h1, 0.f);

    float h2 = s_b2[lane];
    #pragma unroll
    for (int k = 0; k < 32; k++) h2 += __shfl_sync(FULLMASK, h1, k) * s_w2[k * 32 + lane];
    h2 = fmaxf(h2, 0.f);

    outp[n * 32 + lane] = h2;

    atomicAdd(&s_sum[lane], h2);
    atomicAdd(&s_sq[lane], h2 * h2);
    __syncthreads();
    if (tid < 32)       atomicAdd(&g_stats[sl_out * 64 + tid], s_sum[tid]);
    else if (tid < 64)  atomicAdd(&g_stats[sl_out * 64 + tid], s_sq[tid - 32]);
}

// ---------------- final fused layer: gather + BN-fold + 32->32->128 --------
__global__ void __launch_bounds__(256) gin_last_fused_kernel(
    const float* __restrict__ xin, float* __restrict__ outp,
    const float* __restrict__ w1, const float* __restrict__ b1,
    const float* __restrict__ w2L, const float* __restrict__ b2L,
    int sl_in, const float* __restrict__ gamma, const float* __restrict__ beta)
{
    __shared__ float s_w1[1024];
    __shared__ float wLs[HID * DIM_IN];
    __shared__ float sa[32], sb[32], s_b1[32];
    int tid = threadIdx.x, lane = tid & 31, wrp = tid >> 5;

    for (int i = tid; i < 1024; i += 256) s_w1[i] = w1[i];
    for (int i = tid; i < HID * DIM_IN; i += 256) wLs[i] = w2L[i];
    if (tid < 32) {
        s_b1[tid] = b1[tid];
        float s = g_stats[sl_in * 64 + tid];
        float q = g_stats[sl_in * 64 + 32 + tid];
        const float invn = 1.f / (float)N_NODES;
        float m = s * invn;
        float v = fmaxf(q * invn - m * m, 0.f);
        float a = gamma[tid] * rsqrtf(v + BN_EPS);
        sa[tid] = a;
        sb[tid] = beta[tid] - a * m;
    }
    __syncthreads();

    int n = blockIdx.x * 8 + wrp;
    int start = g_rowptr[n], end = g_rowptr[n + 1];

    float t = gather_sum(xin, n, start, end, lane);
    t = sa[lane] * t + (float)(end - start + 1) * sb[lane];

    float h1 = s_b1[lane];
    #pragma unroll
    for (int k = 0; k < 32; k++) h1 += __shfl_sync(FULLMASK, t, k) * s_w1[k * 32 + lane];
    h1 = fmaxf(h1, 0.f);

    float o0 = b2L[lane], o1 = b2L[32 + lane], o2 = b2L[64 + lane], o3 = b2L[96 + lane];
    #pragma unroll
    for (int k = 0; k < 32; k++) {
        float hk = __shfl_sync(FULLMASK, h1, k);
        const float* wr = &wLs[k * 128];
        o0 += hk * wr[lane];
        o1 += hk * wr[32 + lane];
        o2 += hk * wr[64 + lane];
        o3 += hk * wr[96 + lane];
    }
    float* orow = outp + (long long)n * 128;
    orow[lane]      = fmaxf(o0, 0.f);
    orow[32 + lane] = fmaxf(o1, 0.f);
    orow[64 + lane] = fmaxf(o2, 0.f);
    orow[96 + lane] = fmaxf(o3, 0.f);
}

// ---------------- BN apply (final encoder output only) ---------------------
__global__ void __launch_bounds__(256) bn_out_kernel(
    const float* __restrict__ pre, float* __restrict__ outp, int sl,
    const float* __restrict__ gamma, const float* __restrict__ beta)
{
    __shared__ float sa[32], sb[32];
    if (threadIdx.x < 32) {
        float s = g_stats[sl * 64 + threadIdx.x];
        float q = g_stats[sl * 64 + 32 + threadIdx.x];
        const float invn = 1.f / (float)N_NODES;
        float m = s * invn;
        float v = fmaxf(q * invn - m * m, 0.f);
        float a = gamma[threadIdx.x] * rsqrtf(v + BN_EPS);
        sa[threadIdx.x] = a;
        sb[threadIdx.x] = beta[threadIdx.x] - a * m;
    }
    __syncthreads();
    int i = blockIdx.x * 256 + threadIdx.x;     // float4 index; exact coverage
    int f0 = (i & 7) * 4;
    float4 v4 = ((const float4*)pre)[i];
    v4.x = sa[f0]     * v4.x + sb[f0];
    v4.y = sa[f0 + 1] * v4.y + sb[f0 + 1];
    v4.z = sa[f0 + 2] * v4.z + sb[f0 + 2];
    v4.w = sa[f0 + 3] * v4.w + sb[f0 + 3];
    ((float4*)outp)[i] = v4;
}

// ---------------- pool of post-BN layer rep (affine of raw pool) -----------
__global__ void __launch_bounds__(256) pool_kernel(
    const float* __restrict__ src, float* __restrict__ dst, int layer, int sl,
    const float* __restrict__ gamma, const float* __restrict__ beta)
{
    __shared__ float sa[32], sb2[32];
    __shared__ float sp[256];
    int tid = threadIdx.x;
    if (tid < 32) {
        float s = g_stats[sl * 64 + tid];
        float q = g_stats[sl * 64 + 32 + tid];
        const float invn = 1.f / (float)N_NODES;
        float m = s * invn;
        float v = fmaxf(q * invn - m * m, 0.f);
        float a = gamma[tid] * rsqrtf(v + BN_EPS);
        sa[tid] = a;
        sb2[tid] = beta[tid] - a * m;
    }
    __syncthreads();
    int g = blockIdx.x;
    int s = g_goff[g], e = g_goff[g + 1];
    int f = tid & 31, sub = tid >> 5;
    float p = 0.f;
    for (int r = s + sub; r < e; r += 8) p += src[r * 32 + f];
    sp[tid] = p;
    __syncthreads();
    if (tid < 32) {
        float t = sp[f];
        #pragma unroll
        for (int j = 1; j < 8; j++) t += sp[j * 32 + f];
        dst[g * (5 * HID) + layer * HID + f] = sa[f] * t + (float)(e - s) * sb2[f];
    }
}

// ---------------- launch ---------------------------------------------------
extern "C" void kernel_launch(void* const* d_in, const int* in_sizes, int n_in,
                              void* d_out, int out_size) {
    const float* x        = (const float*)d_in[0];
    const int*   ei       = (const int*)d_in[1];
    const int*   batch    = (const int*)d_in[2];
    const float* e0_w1    = (const float*)d_in[3];
    const float* e0_b1    = (const float*)d_in[4];
    const float* e0_w2    = (const float*)d_in[5];
    const float* e0_b2    = (const float*)d_in[6];
    const float* enc_w1   = (const float*)d_in[7];
    const float* enc_b1   = (const float*)d_in[8];
    const float* enc_w2   = (const float*)d_in[9];
    const float* enc_b2   = (const float*)d_in[10];
    const float* enc_gamma= (const float*)d_in[11];
    const float* enc_beta = (const float*)d_in[12];
    const float* dec_w1   = (const float*)d_in[13];
    const float* dec_b1   = (const float*)d_in[14];
    const float* dec_w2   = (const float*)d_in[15];
    const float* dec_b2   = (const float*)d_in[16];
    const float* dec_w2_last = (const float*)d_in[17];
    const float* dec_b2_last = (const float*)d_in[18];
    const float* dec_gamma= (const float*)d_in[19];
    const float* dec_beta = (const float*)d_in[20];
    float* out = (float*)d_out;

    const int* srcp = ei;
    const int* dstp = ei + N_EDGES;

    float *pA, *pC, *pXP;
    cudaGetSymbolAddress((void**)&pA,  g_bufA);
    cudaGetSymbolAddress((void**)&pC,  g_bufC);
    cudaGetSymbolAddress((void**)&pXP, g_xp);

    static int s_attr_done = 0;
    if (!s_attr_done) {
        cudaFuncSetAttribute(proj_kernel,
            cudaFuncAttributeMaxDynamicSharedMemorySize, PROJ_SMEM);
        s_attr_done = 1;
    }

    // CSR build + projection
    init_kernel<<<782, 256>>>();
    hist_kernel<<<25000, 256>>>(dstp);
    scan_block_kernel<<<SCAN_BLOCKS, 1024>>>();
    proj_kernel<<<1563, 256, PROJ_SMEM>>>(x, e0_w1);  // launch index 3 (ncu slot)
    scan_tops_kernel<<<1, 256>>>();
    scan_add_kernel<<<SCAN_BLOCKS, 1024>>>();
    offsets_kernel<<<3, 256>>>(batch);
    permute_kernel<<<25000, 256>>>(srcp, dstp);

    float* cur = pXP;
    float* nxt = pA;
    float* alt = pC;

    // ----- encoder (BN folded into next layer's aggregation + pool) -----
    gin_fused_kernel<false, false><<<25000, 256>>>(cur, nxt, nullptr,
        e0_b1, e0_w2, e0_b2, 0, nullptr, nullptr, 0);
    cur = nxt; nxt = alt; alt = cur;   // cur=A, nxt=C
    pool_kernel<<<N_GRAPHS, 256>>>(cur, out + GLOB_OFF, 0, 0, enc_gamma, enc_beta);
    for (int L = 1; L < 5; L++) {
        gin_fused_kernel<true, true><<<25000, 256>>>(cur, nxt,
            enc_w1 + (L - 1) * 1024, enc_b1 + (L - 1) * 32,
            enc_w2 + (L - 1) * 1024, enc_b2 + (L - 1) * 32,
            L - 1, enc_gamma + (L - 1) * 32, enc_beta + (L - 1) * 32, L);
        { float* t = cur; cur = nxt; nxt = t; }
        pool_kernel<<<N_GRAPHS, 256>>>(cur, out + GLOB_OFF, L, L,
            enc_gamma + L * 32, enc_beta + L * 32);
    }
    bn_out_kernel<<<6250, 256>>>(cur, out + ENC_OFF, 4, enc_gamma + 4 * 32, enc_beta + 4 * 32);

    // ----- decoder -----
    for (int L = 0; L < 4; L++) {
        const float* gI = (L == 0) ? (enc_gamma + 4 * 32) : (dec_gamma + (L - 1) * 32);
        const float* bI = (L == 0) ? (enc_beta  + 4 * 32) : (dec_beta  + (L - 1) * 32);
        int slin = (L == 0) ? 4 : (4 + L);
        gin_fused_kernel<true, true><<<25000, 256>>>(cur, nxt,
            dec_w1 + L * 1024, dec_b1 + L * 32,
            dec_w2 + L * 1024, dec_b2 + L * 32,
            slin, gI, bI, 5 + L);
        { float* t = cur; cur = nxt; nxt = t; }
    }
    gin_last_fused_kernel<<<25000, 256>>>(cur, out + DEC_OFF,
        dec_w1 + 4 * 1024, dec_b1 + 4 * 32, dec_w2_last, dec_b2_last,
        8, dec_gamma + 3 * 32, dec_beta + 3 * 32);
}